// round 4
// baseline (speedup 1.0000x reference)
#include <cuda_runtime.h>
#include <math.h>
#include <stdint.h>

#define NB 2
#define NV 6
#define NC 256
#define NQ 900
#define NM (NB*NQ)       // 1800 rows
#define NH 8
#define HDIM 32

#define NEG_INF (__int_as_float(0xff800000))

// Scratch (no allocations allowed)
__device__ float g_ctx[NM*NC];
__device__ float g_q[NM*NC];
__device__ float g_k[NM*NC];
__device__ float g_v[NM*NC];
__device__ float g_o[NM*NC];

// ---------------------------------------------------------------------------
// Sampler (unchanged): one block per (b,q); gather only in-bounds taps.
// ---------------------------------------------------------------------------
__global__ __launch_bounds__(256) void sampler_kernel(
    const float* __restrict__ f0, const float* __restrict__ f1,
    const float* __restrict__ refs, const float* __restrict__ intr,
    const float* __restrict__ extr)
{
    const int q = blockIdx.x, b = blockIdx.y;
    __shared__ int   s_off[48][4];
    __shared__ float s_w[48][4];
    __shared__ int   s_valid[48];
    __shared__ int   s_any[48];
    const int t = threadIdx.x;

    if (t < 48) {
        const int lvl = t / 24, rem = t % 24, v = rem >> 2, kp = rem & 3;
        const float kxs[4] = {0.f, 2.f, 0.f, -2.f};
        const float kys[4] = {0.f, 0.f, 2.f, 0.f};
        const float* rp = refs + ((size_t)b*NQ + q)*3;
        float px = rp[0] + kxs[kp], py = rp[1] + kys[kp], pz = rp[2];
        const float* E = extr + ((size_t)b*NV + v)*16;
        float cx = E[0]*px + E[1]*py + E[2]*pz  + E[3];
        float cy = E[4]*px + E[5]*py + E[6]*pz  + E[7];
        float cz = E[8]*px + E[9]*py + E[10]*pz + E[11];
        const float* I = intr + ((size_t)b*NV + v)*9;
        float u  = I[0]*cx + I[1]*cy + I[2]*cz;
        float vv = I[3]*cx + I[4]*cy + I[5]*cz;
        float w  = I[6]*cx + I[7]*cy + I[8]*cz;
        float zs = (fabsf(w) > 1e-6f) ? w : 1e-6f;
        const int Wd = lvl ? 88 : 176, Hd = lvl ? 32 : 64;
        float gx = 2.f*(u/zs)/(float)(Wd-1) - 1.f;
        float gy = 2.f*(vv/zs)/(float)(Hd-1) - 1.f;
        float x = (gx + 1.f)*0.5f*(float)(Wd-1);
        float y = (gy + 1.f)*0.5f*(float)(Hd-1);
        float x0 = floorf(x), y0 = floorf(y);
        float wx1 = x - x0, wx0 = 1.f - wx1;
        float wy1 = y - y0, wy0 = 1.f - wy1;
        const int valid = (w > 0.f) ? 1 : 0;
        s_valid[t] = valid;
        int any = 0;
        #pragma unroll
        for (int ti = 0; ti < 4; ti++) {
            float xi = (ti & 1) ? x0 + 1.f : x0;
            float yi = (ti & 2) ? y0 + 1.f : y0;
            float wt = ((ti & 1) ? wx1 : wx0) * ((ti & 2) ? wy1 : wy0);
            bool inb = (xi >= 0.f) && (xi <= (float)(Wd-1)) &&
                       (yi >= 0.f) && (yi <= (float)(Hd-1));
            if (valid && inb && wt != 0.f) {
                s_off[t][ti] = (int)yi * Wd + (int)xi;
                s_w[t][ti]   = wt;
                any = 1;
            } else {
                s_off[t][ti] = -1;
            }
        }
        s_any[t] = any;
    }
    __syncthreads();

    float acc0 = 0.f, acc1 = 0.f;
    for (int p = 0; p < 48; p++) {
        if (!s_any[p]) continue;
        const int lvl = (p >= 24) ? 1 : 0;
        const int rem = p - lvl*24, v = rem >> 2;
        const float* fb = lvl ? f1 + ((size_t)((b*NV + v)*NC + t))*(32*88)
                              : f0 + ((size_t)((b*NV + v)*NC + t))*(64*176);
        float a = 0.f;
        #pragma unroll
        for (int ti = 0; ti < 4; ti++) {
            int off = s_off[p][ti];
            if (off >= 0) a += s_w[p][ti] * __ldg(fb + off);
        }
        if (lvl) acc1 += a; else acc0 += a;
    }
    int cnt0 = 0, cnt1 = 0;
    #pragma unroll
    for (int p = 0; p < 24; p++) cnt0 += s_valid[p];
    #pragma unroll
    for (int p = 24; p < 48; p++) cnt1 += s_valid[p];
    float r = 0.5f * (acc0 / fmaxf((float)cnt0, 1.f) +
                      acc1 / fmaxf((float)cnt1, 1.f));
    g_ctx[((size_t)b*NQ + q)*NC + t] = r;
}

// ---------------------------------------------------------------------------
// tf32 tensor-core GEMM (NT): C[M,256] = A[M,256]*W[256,256]^T + bias.
// 32x32 block tile, 128 threads (2x2 warps, each 16Mx16N), BK=32,
// mma.sync.m16n8k8. smem row stride 36 (mod 32 == 4) -> conflict-free frags.
// ---------------------------------------------------------------------------
__device__ __forceinline__ uint32_t f2tf(float f) {
    uint32_t r;
    asm("cvt.rna.tf32.f32 %0, %1;" : "=r"(r) : "f"(f));
    return r;
}

__device__ __forceinline__ void mma_tf32(
    float& c0, float& c1, float& c2, float& c3,
    uint32_t a0, uint32_t a1, uint32_t a2, uint32_t a3,
    uint32_t b0, uint32_t b1)
{
    asm volatile(
        "mma.sync.aligned.m16n8k8.row.col.f32.tf32.tf32.f32 "
        "{%0,%1,%2,%3}, {%4,%5,%6,%7}, {%8,%9}, {%0,%1,%2,%3};"
        : "+f"(c0), "+f"(c1), "+f"(c2), "+f"(c3)
        : "r"(a0), "r"(a1), "r"(a2), "r"(a3), "r"(b0), "r"(b1));
}

__device__ __forceinline__ void gemm_tf32_core(
    const float* __restrict__ A, const float* __restrict__ Wm,
    const float* __restrict__ bias, float* __restrict__ C,
    int M, int m0, int n0)
{
    const int K = 256;
    __shared__ __align__(16) uint32_t As[32][36];
    __shared__ __align__(16) uint32_t Ws[32][36];
    const int t = threadIdx.x;
    const int lane = t & 31, wid = t >> 5;
    const int wm = (wid >> 1) * 16;       // warp M offset (0/16)
    const int wn = (wid & 1) * 16;        // warp N offset (0/16)
    const int gid = lane >> 2, tig = lane & 3;

    float c[2][4] = {};

    for (int k0 = 0; k0 < K; k0 += 32) {
        // stage A and W tiles (tf32-converted). 256 float4 each; 2 per thread.
        #pragma unroll
        for (int i = 0; i < 2; i++) {
            const int id = t + i * 128;
            const int r = id >> 3, kk = (id & 7) * 4;
            float4 av = make_float4(0.f, 0.f, 0.f, 0.f);
            if (m0 + r < M)
                av = *(const float4*)(A + (size_t)(m0 + r)*K + k0 + kk);
            uint4 at;
            at.x = f2tf(av.x); at.y = f2tf(av.y);
            at.z = f2tf(av.z); at.w = f2tf(av.w);
            *(uint4*)&As[r][kk] = at;
            float4 wv = *(const float4*)(Wm + (size_t)(n0 + r)*K + k0 + kk);
            uint4 wt;
            wt.x = f2tf(wv.x); wt.y = f2tf(wv.y);
            wt.z = f2tf(wv.z); wt.w = f2tf(wv.w);
            *(uint4*)&Ws[r][kk] = wt;
        }
        __syncthreads();

        #pragma unroll
        for (int ks = 0; ks < 32; ks += 8) {
            const int arow = wm + gid;
            uint32_t a0 = As[arow    ][ks + tig];
            uint32_t a1 = As[arow + 8][ks + tig];
            uint32_t a2 = As[arow    ][ks + tig + 4];
            uint32_t a3 = As[arow + 8][ks + tig + 4];
            #pragma unroll
            for (int nt = 0; nt < 2; nt++) {
                const int nrow = wn + nt*8 + gid;
                uint32_t b0 = Ws[nrow][ks + tig];
                uint32_t b1 = Ws[nrow][ks + tig + 4];
                mma_tf32(c[nt][0], c[nt][1], c[nt][2], c[nt][3],
                         a0, a1, a2, a3, b0, b1);
            }
        }
        __syncthreads();
    }

    // epilogue: c0=[row][2*tig], c1=[row][2*tig+1], c2/c3 at row+8
    const int row = m0 + wm + gid;
    #pragma unroll
    for (int nt = 0; nt < 2; nt++) {
        const int n = n0 + wn + nt*8 + tig*2;
        const float b0 = bias[n], b1 = bias[n + 1];
        if (row < M) {
            C[(size_t)row*256 + n    ] = c[nt][0] + b0;
            C[(size_t)row*256 + n + 1] = c[nt][1] + b1;
        }
        if (row + 8 < M) {
            C[(size_t)(row + 8)*256 + n    ] = c[nt][2] + b0;
            C[(size_t)(row + 8)*256 + n + 1] = c[nt][3] + b1;
        }
    }
}

// Fused Q/K/V projections: blockIdx.z selects {A, W, bias, C}
__global__ __launch_bounds__(128) void gemm_qkv_kernel(
    const float* __restrict__ qin, const float* __restrict__ ctx,
    const float* __restrict__ Wq, const float* __restrict__ bq,
    const float* __restrict__ Wk, const float* __restrict__ bk,
    const float* __restrict__ Wv, const float* __restrict__ bv,
    float* __restrict__ Cq, float* __restrict__ Ck, float* __restrict__ Cv)
{
    const int z = blockIdx.z;
    const float* A  = (z == 0) ? qin : ctx;
    const float* W  = (z == 0) ? Wq : (z == 1) ? Wk : Wv;
    const float* bi = (z == 0) ? bq : (z == 1) ? bk : bv;
    float* C        = (z == 0) ? Cq : (z == 1) ? Ck : Cv;
    gemm_tf32_core(A, W, bi, C, NM, blockIdx.y * 32, blockIdx.x * 32);
}

__global__ __launch_bounds__(128) void gemm_nt_kernel(
    const float* __restrict__ A, const float* __restrict__ Wm,
    const float* __restrict__ bias, float* __restrict__ C, int M)
{
    gemm_tf32_core(A, Wm, bias, C, M, blockIdx.y * 32, blockIdx.x * 32);
}

// ---------------------------------------------------------------------------
// Attention: block = 32 q-rows x 4 key-splits (128 thr). float4 smem reads.
// ---------------------------------------------------------------------------
__global__ __launch_bounds__(128) void attn_kernel(
    const float* __restrict__ gq, const float* __restrict__ gk,
    const float* __restrict__ gv, float* __restrict__ go)
{
    const int D = NC;
    const float scale = 0.17677669529663687f;   // 1/sqrt(32)
    const int b = blockIdx.z, h = blockIdx.y;
    const int m0 = blockIdx.x * 32;
    const int tid = threadIdx.x;
    const int lane = tid & 31, wrp = tid >> 5;
    const int m = m0 + lane;
    const bool act = (m < NQ);

    __shared__ float sk[64][32];
    __shared__ float sv[64][32];
    __shared__ float s_m[4][32];
    __shared__ float s_l[4][32];
    __shared__ float s_o[4][32][33];

    float qreg[HDIM];
    #pragma unroll
    for (int d = 0; d < HDIM; d++)
        qreg[d] = act ? gq[((size_t)(b*NQ + m))*D + h*HDIM + d] : 0.f;

    float mx = NEG_INF, l = 0.f;
    float o[HDIM];
    #pragma unroll
    for (int d = 0; d < HDIM; d++) o[d] = 0.f;

    for (int k0 = 0; k0 < NQ; k0 += 64) {
        const int kn = min(64, NQ - k0);
        __syncthreads();
        for (int i = tid; i < 512; i += 128) {
            int r = i >> 3, sg = i & 7;
            float4 kv = make_float4(0.f,0.f,0.f,0.f);
            float4 vv = make_float4(0.f,0.f,0.f,0.f);
            if (r < kn) {
                size_t base = ((size_t)(b*NQ + k0 + r))*D + h*HDIM + sg*4;
                kv = *(const float4*)(gk + base);
                vv = *(const float4*)(gv + base);
            }
            *(float4*)&sk[r][sg*4] = kv;
            *(float4*)&sv[r][sg*4] = vv;
        }
        __syncthreads();

        float sc[16];
        float tmax = NEG_INF;
        #pragma unroll
        for (int jj = 0; jj < 16; jj++) {
            int j = wrp*16 + jj;
            float s;
            if (j < kn) {
                const float4* k4 = (const float4*)&sk[j][0];
                s = 0.f;
                #pragma unroll
                for (int g = 0; g < 8; g++) {
                    float4 kv = k4[g];
                    s += qreg[4*g+0]*kv.x + qreg[4*g+1]*kv.y
                       + qreg[4*g+2]*kv.z + qreg[4*g+3]*kv.w;
                }
                s *= scale;
            } else {
                s = NEG_INF;
            }
            sc[jj] = s;
            tmax = fmaxf(tmax, s);
        }
        float mnew = fmaxf(mx, tmax);
        float corr = __expf(mx - mnew);
        l *= corr;
        #pragma unroll
        for (int d = 0; d < HDIM; d++) o[d] *= corr;
        #pragma unroll
        for (int jj = 0; jj < 16; jj++) {
            int j = wrp*16 + jj;
            float p = __expf(sc[jj] - mnew);
            l += p;
            const float4* v4 = (const float4*)&sv[j][0];
            #pragma unroll
            for (int g = 0; g < 8; g++) {
                float4 vv = v4[g];
                o[4*g+0] += p * vv.x;
                o[4*g+1] += p * vv.y;
                o[4*g+2] += p * vv.z;
                o[4*g+3] += p * vv.w;
            }
        }
        mx = mnew;
    }

    // merge the 4 key-splits
    s_m[wrp][lane] = mx;
    s_l[wrp][lane] = l;
    #pragma unroll
    for (int d = 0; d < HDIM; d++) s_o[wrp][lane][d] = o[d];
    __syncthreads();

    if (wrp == 0 && act) {
        float M2 = s_m[0][lane];
        #pragma unroll
        for (int s = 1; s < 4; s++) M2 = fmaxf(M2, s_m[s][lane]);
        float L = 0.f;
        float out[HDIM];
        #pragma unroll
        for (int d = 0; d < HDIM; d++) out[d] = 0.f;
        #pragma unroll
        for (int s = 0; s < 4; s++) {
            float w = __expf(s_m[s][lane] - M2);
            L += s_l[s][lane] * w;
            #pragma unroll
            for (int d = 0; d < HDIM; d++) out[d] += w * s_o[s][lane][d];
        }
        float invL = 1.f / L;
        #pragma unroll
        for (int d = 0; d < HDIM; d++)
            go[((size_t)(b*NQ + m))*D + h*HDIM + d] = out[d] * invL;
    }
}

// ---------------------------------------------------------------------------
extern "C" void kernel_launch(void* const* d_in, const int* in_sizes, int n_in,
                              void* d_out, int out_size)
{
    const float* f0   = (const float*)d_in[0];
    const float* f1   = (const float*)d_in[1];
    const float* refs = (const float*)d_in[2];
    const float* intr = (const float*)d_in[3];
    const float* extr = (const float*)d_in[4];
    const float* qin  = (const float*)d_in[5];
    const float* Wq   = (const float*)d_in[6];
    const float* bq   = (const float*)d_in[7];
    const float* Wk   = (const float*)d_in[8];
    const float* bk   = (const float*)d_in[9];
    const float* Wv   = (const float*)d_in[10];
    const float* bv   = (const float*)d_in[11];
    const float* Wo   = (const float*)d_in[12];
    const float* bo   = (const float*)d_in[13];
    float* out = (float*)d_out;

    float *p_ctx, *p_q, *p_k, *p_v, *p_o;
    cudaGetSymbolAddress((void**)&p_ctx, g_ctx);
    cudaGetSymbolAddress((void**)&p_q,   g_q);
    cudaGetSymbolAddress((void**)&p_k,   g_k);
    cudaGetSymbolAddress((void**)&p_v,   g_v);
    cudaGetSymbolAddress((void**)&p_o,   g_o);

    sampler_kernel<<<dim3(NQ, NB), 256>>>(f0, f1, refs, intr, extr);

    dim3 qkvgrid(8, (NM + 31)/32, 3);     // n-tiles, m-tiles, {q,k,v}
    gemm_qkv_kernel<<<qkvgrid, 128>>>(qin, p_ctx, Wq, bq, Wk, bk, Wv, bv,
                                      p_q, p_k, p_v);

    attn_kernel<<<dim3((NQ + 31)/32, NH, NB), 128>>>(p_q, p_k, p_v, p_o);

    dim3 ggrid(8, (NM + 31)/32);
    gemm_nt_kernel<<<ggrid, 128>>>(p_o, Wo, bo, out, NM);
}